// round 7
// baseline (speedup 1.0000x reference)
#include <cuda_runtime.h>
#include <math.h>
#include <stdint.h>

// ---------------- problem constants ----------------
#define SEQ     2048
#define BATCH   2
#define DMODEL  2048
#define NHEADS  16
#define DH      128
#define NOPE    64
#define ROPE_D  64
#define QPROJ   1024
#define KVPROJ  1365
#define CKV_COLS 1429          // KVPROJ + ROPE_D
#define KVOUT   3072           // NHEADS * (DH + NOPE) = 16*192
#define MROWS   (BATCH*SEQ)    // 4096
#define KVHEAD  192            // DH + NOPE per head in KV

// ---------------- scratch (static __device__ arrays: allowed) ----------------
__device__ float g_cq[(size_t)MROWS*QPROJ];
__device__ float g_Q[(size_t)MROWS*DMODEL];
__device__ float g_kvlora[(size_t)MROWS*KVPROJ];
__device__ float g_KV[(size_t)MROWS*KVOUT];
__device__ float g_Krope[(size_t)MROWS*ROPE_D];
__device__ float g_attnout[(size_t)MROWS*DMODEL];

// buffer selectors (resolved in DEVICE code -> host never needs symbol addresses)
#define BUF_CQ    0
#define BUF_Q     1
#define BUF_KVL   2
#define BUF_KV    3
#define BUF_KROPE 4
#define BUF_AOUT  5

__device__ __forceinline__ float* sel_buf(int s) {
    switch (s) {
        case BUF_CQ:    return g_cq;
        case BUF_Q:     return g_Q;
        case BUF_KVL:   return g_kvlora;
        case BUF_KV:    return g_KV;
        case BUF_KROPE: return g_Krope;
        default:        return g_attnout;
    }
}

// =====================================================================
// Generic guarded fp32 GEMM: C[M,N] = A[M,K] @ B  (B is [K,N], or [N,K] if TRANSB)
// 128x128 block tile, BK=16, 256 threads, 8x8 microtile.
// aSel/cSel >= 0 select an internal scratch buffer; -1 = use external ptr.
// =====================================================================
template<bool TRANSB>
__global__ __launch_bounds__(256)
void gemm_kernel(const float* __restrict__ Aext, const float* __restrict__ B,
                 float* __restrict__ Cext, int aSel, int cSel,
                 int M, int N, int K)
{
    const float* __restrict__ A = (aSel >= 0) ? sel_buf(aSel) : Aext;
    float* __restrict__       C = (cSel >= 0) ? sel_buf(cSel) : Cext;

    __shared__ float As[16*132];   // As[k][m], stride 132 to break conflicts
    __shared__ float Bs[16*132];   // Bs[k][n]

    const int tid = threadIdx.x;
    const int tx  = tid & 15;      // col group
    const int ty  = tid >> 4;      // row group
    const int m0  = blockIdx.y * 128;
    const int n0  = blockIdx.x * 128;

    float acc[8][8];
#pragma unroll
    for (int i = 0; i < 8; i++)
#pragma unroll
        for (int j = 0; j < 8; j++) acc[i][j] = 0.f;

    const int nk = (K + 15) >> 4;
    for (int kt = 0; kt < nk; ++kt) {
        const int k0 = kt * 16;
        // load A tile (transposed into smem): As[k][m]
#pragma unroll
        for (int i = 0; i < 8; i++) {
            int idx = i * 256 + tid;
            int k = idx & 15, m = idx >> 4;
            int gm = m0 + m, gk = k0 + k;
            As[k*132 + m] = (gm < M && gk < K) ? A[(size_t)gm * K + gk] : 0.f;
        }
        // load B tile: Bs[k][n]
        if (!TRANSB) {
#pragma unroll
            for (int i = 0; i < 8; i++) {
                int idx = i * 256 + tid;
                int n = idx & 127, k = idx >> 7;
                int gn = n0 + n, gk = k0 + k;
                Bs[k*132 + n] = (gn < N && gk < K) ? B[(size_t)gk * N + gn] : 0.f;
            }
        } else {
#pragma unroll
            for (int i = 0; i < 8; i++) {
                int idx = i * 256 + tid;
                int k = idx & 15, n = idx >> 4;
                int gn = n0 + n, gk = k0 + k;
                Bs[k*132 + n] = (gn < N && gk < K) ? B[(size_t)gn * K + gk] : 0.f;
            }
        }
        __syncthreads();

#pragma unroll
        for (int k = 0; k < 16; k++) {
            float a[8], b[8];
            *(float4*)&a[0] = *(const float4*)&As[k*132 + ty*8];
            *(float4*)&a[4] = *(const float4*)&As[k*132 + ty*8 + 4];
            *(float4*)&b[0] = *(const float4*)&Bs[k*132 + tx*8];
            *(float4*)&b[4] = *(const float4*)&Bs[k*132 + tx*8 + 4];
#pragma unroll
            for (int i = 0; i < 8; i++)
#pragma unroll
                for (int j = 0; j < 8; j++) acc[i][j] = fmaf(a[i], b[j], acc[i][j]);
        }
        __syncthreads();
    }

    // float4 epilogue only when every STG.128 is 16B-aligned: requires N % 4 == 0
    // AND a fully in-bounds tile (the N=1429 GEMM must always take the scalar path).
    const bool full = (m0 + 128 <= M) && (n0 + 128 <= N) && ((N & 3) == 0);
    if (full) {
#pragma unroll
        for (int i = 0; i < 8; i++) {
            size_t base = (size_t)(m0 + ty*8 + i) * N + n0 + tx*8;
            *(float4*)&C[base]     = *(float4*)&acc[i][0];
            *(float4*)&C[base + 4] = *(float4*)&acc[i][4];
        }
    } else {
#pragma unroll
        for (int i = 0; i < 8; i++) {
            int row = m0 + ty*8 + i;
            if (row >= M) continue;
#pragma unroll
            for (int j = 0; j < 8; j++) {
                int col = n0 + tx*8 + j;
                if (col < N) C[(size_t)row * N + col] = acc[i][j];
            }
        }
    }
}

// =====================================================================
// Row LayerNorm: y = (x - mean)/sqrt(var + eps) * w + b
// one block (256 thr) per row
// =====================================================================
__global__ __launch_bounds__(256)
void ln_kernel(const float* __restrict__ inExt, float* __restrict__ outExt,
               int inSel, int outSel,
               const float* __restrict__ w, const float* __restrict__ b,
               int cols, int in_stride, int out_stride)
{
    const float* in  = (inSel  >= 0) ? sel_buf(inSel)  : inExt;
    float*       out = (outSel >= 0) ? sel_buf(outSel) : outExt;

    __shared__ float rs[32], rs2[32];
    const size_t row = blockIdx.x;
    const float* x = in  + row * (size_t)in_stride;
    float*       y = out + row * (size_t)out_stride;

    float s = 0.f, s2 = 0.f;
    for (int c = threadIdx.x; c < cols; c += blockDim.x) {
        float v = x[c]; s += v; s2 += v * v;
    }
#pragma unroll
    for (int o = 16; o; o >>= 1) {
        s  += __shfl_xor_sync(0xffffffffu, s,  o);
        s2 += __shfl_xor_sync(0xffffffffu, s2, o);
    }
    int lane = threadIdx.x & 31, wid = threadIdx.x >> 5;
    if (lane == 0) { rs[wid] = s; rs2[wid] = s2; }
    __syncthreads();
    if (wid == 0) {
        int nw = blockDim.x >> 5;
        s  = (lane < nw) ? rs[lane]  : 0.f;
        s2 = (lane < nw) ? rs2[lane] : 0.f;
#pragma unroll
        for (int o = 16; o; o >>= 1) {
            s  += __shfl_xor_sync(0xffffffffu, s,  o);
            s2 += __shfl_xor_sync(0xffffffffu, s2, o);
        }
        if (lane == 0) { rs[0] = s; rs2[0] = s2; }
    }
    __syncthreads();
    float mean = rs[0] / (float)cols;
    float var  = rs2[0] / (float)cols - mean * mean;
    float inv  = rsqrtf(var + 1e-5f);
    for (int c = threadIdx.x; c < cols; c += blockDim.x)
        y[c] = (x[c] - mean) * inv * w[c] + b[c];
}

// =====================================================================
// RoPE on Q (g_Q, in place). Q layout: [b*S+s, h*128 + d], rope d in [64,128).
// 512 threads = 16 heads x 32 lanes, one block per (b,s).
// =====================================================================
__global__ __launch_bounds__(512)
void rope_q_kernel()
{
    int bs = blockIdx.x;
    int s  = bs & (SEQ - 1);
    int h  = threadIdx.x >> 5;
    int j  = threadIdx.x & 31;
    double f   = pow(10000.0, -(double)j / 64.0);
    double ang = (double)s * f;
    double cd, sd; sincos(ang, &sd, &cd);
    float c = (float)cd, sn = (float)sd;
    float* q = g_Q + (size_t)bs * DMODEL + h * DH + NOPE;
    float x1 = q[j], x2 = q[j + 32];
    q[j]      = x1 * c - x2 * sn;
    q[j + 32] = x2 * c + x1 * sn;
}

// RoPE on K_rope: read compressed_kv[:, 1365:1429] -> g_Krope[b*S+s, 64]
__global__ __launch_bounds__(32)
void rope_k_kernel(const float* __restrict__ ckv)
{
    int bs = blockIdx.x;
    int s  = bs & (SEQ - 1);
    int j  = threadIdx.x;
    double f   = pow(10000.0, -(double)j / 64.0);
    double ang = (double)s * f;
    double cd, sd; sincos(ang, &sd, &cd);
    float c = (float)cd, sn = (float)sd;
    const float* src = ckv + (size_t)bs * CKV_COLS + KVPROJ;
    float x1 = src[j], x2 = src[j + 32];
    float* dst = g_Krope + (size_t)bs * ROPE_D;
    dst[j]      = x1 * c - x2 * sn;
    dst[j + 32] = x2 * c + x1 * sn;
}

// =====================================================================
// Flash attention (causal). BM=BN=64, dh=128 (qk and v).
// Q = g_Q, K = [KV cols 0..63 | g_Krope], V = KV cols 64..191, Out = g_attnout.
// grid: (S/64, NHEADS, BATCH), 256 threads. Dynamic smem 118784 B.
// =====================================================================
#define FL_KSTR 136
#define FLASH_SMEM ((64*128 + 64*FL_KSTR + 64*FL_KSTR + 64*64) * 4)

__global__ __launch_bounds__(256)
void flash_kernel()
{
    extern __shared__ float sm[];
    float* Qs = sm;                   // [64][128]
    float* Ks = Qs + 64*128;          // [64][136]
    float* Vs = Ks + 64*FL_KSTR;      // [64][136]
    float* Ps = Vs + 64*FL_KSTR;      // [64][64]

    const float* __restrict__ Q     = g_Q;
    const float* __restrict__ KV    = g_KV;
    const float* __restrict__ Krope = g_Krope;
    float*       __restrict__ Out   = g_attnout;

    const int q0 = blockIdx.x * 64;
    const int h  = blockIdx.y;
    const int b  = blockIdx.z;
    const int tid = threadIdx.x;
    const int tx = tid & 15;          // key-col / dim group
    const int ty = tid >> 4;          // query-row group (4 rows each)
    const float scale = 0.08838834764831845f;  // 1/sqrt(128)

    // stage Q tile
    for (int i = tid; i < 64 * 128; i += 256) {
        int r = i >> 7, c = i & 127;
        Qs[i] = Q[((size_t)(b * SEQ + q0 + r)) * DMODEL + h * DH + c];
    }

    float m[4], l[4], O[4][8];
#pragma unroll
    for (int i = 0; i < 4; i++) {
        m[i] = -1e30f; l[i] = 0.f;
#pragma unroll
        for (int j = 0; j < 8; j++) O[i][j] = 0.f;
    }
    __syncthreads();

    const int ktiles = blockIdx.x + 1;
    for (int kt = 0; kt < ktiles; ++kt) {
        const int k0 = kt * 64;
        // stage K (nope|rope) and V tiles
        for (int i = tid; i < 64 * 128; i += 256) {
            int r = i >> 7, c = i & 127;
            size_t row = (size_t)(b * SEQ + k0 + r);
            float kv = (c < 64) ? KV[row * KVOUT + h * KVHEAD + c]
                                : Krope[row * ROPE_D + (c - 64)];
            Ks[r * FL_KSTR + c] = kv;
            Vs[r * FL_KSTR + c] = KV[row * KVOUT + h * KVHEAD + NOPE + c];
        }
        __syncthreads();

        // scores: rows ty*4..+3, cols tx*4..+3
        float sc[4][4];
#pragma unroll
        for (int i = 0; i < 4; i++)
#pragma unroll
            for (int j = 0; j < 4; j++) sc[i][j] = 0.f;

        for (int k = 0; k < 128; k += 4) {
            float4 qa[4], kb[4];
#pragma unroll
            for (int i = 0; i < 4; i++) qa[i] = *(const float4*)&Qs[(ty*4 + i)*128 + k];
#pragma unroll
            for (int j = 0; j < 4; j++) kb[j] = *(const float4*)&Ks[(tx*4 + j)*FL_KSTR + k];
#pragma unroll
            for (int i = 0; i < 4; i++)
#pragma unroll
                for (int j = 0; j < 4; j++) {
                    sc[i][j] = fmaf(qa[i].x, kb[j].x, sc[i][j]);
                    sc[i][j] = fmaf(qa[i].y, kb[j].y, sc[i][j]);
                    sc[i][j] = fmaf(qa[i].z, kb[j].z, sc[i][j]);
                    sc[i][j] = fmaf(qa[i].w, kb[j].w, sc[i][j]);
                }
        }

        // mask + online softmax update
#pragma unroll
        for (int i = 0; i < 4; i++) {
            int qi = q0 + ty*4 + i;
            float rowmax = -1e30f;
#pragma unroll
            for (int j = 0; j < 4; j++) {
                int kj = k0 + tx*4 + j;
                sc[i][j] = (kj <= qi) ? sc[i][j] * scale : -1e30f;
                rowmax = fmaxf(rowmax, sc[i][j]);
            }
#pragma unroll
            for (int o = 1; o < 16; o <<= 1)
                rowmax = fmaxf(rowmax, __shfl_xor_sync(0xffffffffu, rowmax, o, 16));
            float mnew = fmaxf(m[i], rowmax);
            float fac  = __expf(m[i] - mnew);
            float rsum = 0.f;
#pragma unroll
            for (int j = 0; j < 4; j++) {
                float p = __expf(sc[i][j] - mnew);
                Ps[(ty*4 + i)*64 + tx*4 + j] = p;
                rsum += p;
            }
#pragma unroll
            for (int o = 1; o < 16; o <<= 1)
                rsum += __shfl_xor_sync(0xffffffffu, rsum, o, 16);
            l[i] = l[i] * fac + rsum;
            m[i] = mnew;
#pragma unroll
            for (int j = 0; j < 8; j++) O[i][j] *= fac;
        }
        __syncthreads();

        // O += P @ V   (this thread: 4 rows x dims tx*8..+7)
        for (int kc = 0; kc < 64; kc++) {
            float4 v0 = *(const float4*)&Vs[kc*FL_KSTR + tx*8];
            float4 v1 = *(const float4*)&Vs[kc*FL_KSTR + tx*8 + 4];
#pragma unroll
            for (int i = 0; i < 4; i++) {
                float p = Ps[(ty*4 + i)*64 + kc];
                O[i][0] = fmaf(p, v0.x, O[i][0]);
                O[i][1] = fmaf(p, v0.y, O[i][1]);
                O[i][2] = fmaf(p, v0.z, O[i][2]);
                O[i][3] = fmaf(p, v0.w, O[i][3]);
                O[i][4] = fmaf(p, v1.x, O[i][4]);
                O[i][5] = fmaf(p, v1.y, O[i][5]);
                O[i][6] = fmaf(p, v1.z, O[i][6]);
                O[i][7] = fmaf(p, v1.w, O[i][7]);
            }
        }
        __syncthreads();
    }

#pragma unroll
    for (int i = 0; i < 4; i++) {
        float inv = 1.f / l[i];
        size_t base = ((size_t)(b * SEQ + q0 + ty*4 + i)) * DMODEL + h * DH + tx*8;
#pragma unroll
        for (int j = 0; j < 8; j++) Out[base + j] = O[i][j] * inv;
    }
}

// =====================================================================
// Launch: NOTHING but kernel launches (+ idempotent func attribute).
// No symbol lookups, no memcpy, no static state.
// =====================================================================
extern "C" void kernel_launch(void* const* d_in, const int* in_sizes, int n_in,
                              void* d_out, int out_size)
{
    const float* x       = (const float*)d_in[0];
    const float* W_dq    = (const float*)d_in[1];
    const float* W_uq    = (const float*)d_in[2];
    const float* q_ln_w  = (const float*)d_in[3];
    const float* q_ln_b  = (const float*)d_in[4];
    const float* W_dkv   = (const float*)d_in[5];
    const float* W_ukv   = (const float*)d_in[6];
    const float* kv_ln_w = (const float*)d_in[7];
    const float* kv_ln_b = (const float*)d_in[8];
    const float* W_o     = (const float*)d_in[9];

    float* out = (float*)d_out;                      // [4096, 2048]
    float* ckv = out + (size_t)MROWS * DMODEL;       // [4096, 1429] compressed_kv

    // non-stream API, idempotent, capture-safe
    cudaFuncSetAttribute(flash_kernel,
                         cudaFuncAttributeMaxDynamicSharedMemorySize, FLASH_SMEM);

    dim3 tb(256);

    // 1) cq_pre = x @ W_dq  -> g_cq
    gemm_kernel<false><<<dim3(QPROJ/128, MROWS/128), tb>>>(
        x, W_dq, nullptr, -1, BUF_CQ, MROWS, QPROJ, DMODEL);
    // 2) cq = LN(cq_pre)  (in place on g_cq)
    ln_kernel<<<MROWS, 256>>>(nullptr, nullptr, BUF_CQ, BUF_CQ,
                              q_ln_w, q_ln_b, QPROJ, QPROJ, QPROJ);
    // 3) Q = cq @ W_uq  -> g_Q
    gemm_kernel<false><<<dim3(DMODEL/128, MROWS/128), tb>>>(
        nullptr, W_uq, nullptr, BUF_CQ, BUF_Q, MROWS, DMODEL, QPROJ);
    // 4) RoPE(Q) in place
    rope_q_kernel<<<MROWS, 512>>>();
    // 5) compressed_kv = x @ W_dkv  (straight into d_out tail; scalar epilogue, N odd)
    gemm_kernel<false><<<dim3((CKV_COLS+127)/128, MROWS/128), tb>>>(
        x, W_dkv, ckv, -1, -1, MROWS, CKV_COLS, DMODEL);
    // 6) kv_lora = LN(compressed_kv[:, :1365])  -> g_kvlora
    ln_kernel<<<MROWS, 256>>>(ckv, nullptr, -1, BUF_KVL,
                              kv_ln_w, kv_ln_b, KVPROJ, CKV_COLS, KVPROJ);
    // 7) K_rope = RoPE(compressed_kv[:, 1365:])  -> g_Krope
    rope_k_kernel<<<MROWS, 32>>>(ckv);
    // 8) KV = kv_lora @ W_ukv  -> g_KV
    gemm_kernel<false><<<dim3(KVOUT/128, MROWS/128), tb>>>(
        nullptr, W_ukv, nullptr, BUF_KVL, BUF_KV, MROWS, KVOUT, KVPROJ);
    // 9) causal flash attention -> g_attnout
    flash_kernel<<<dim3(SEQ/64, NHEADS, BATCH), tb, FLASH_SMEM>>>();
    // 10) out = attn_out @ W_o^T
    gemm_kernel<true><<<dim3(DMODEL/128, MROWS/128), tb>>>(
        nullptr, W_o, out, BUF_AOUT, -1, MROWS, DMODEL, DMODEL);
}

// round 10
// speedup vs baseline: 1.5223x; 1.5223x over previous
#include <cuda_runtime.h>
#include <cuda_bf16.h>
#include <math.h>
#include <stdint.h>

// ---------------- problem constants ----------------
#define SEQ     2048
#define BATCH   2
#define DMODEL  2048
#define NHEADS  16
#define DH      128
#define NOPE    64
#define ROPE_D  64
#define QPROJ   1024
#define KVPROJ  1365
#define CKV_COLS 1429          // KVPROJ + ROPE_D
#define KVOUT   3072           // NHEADS * (DH + NOPE) = 16*192
#define MROWS   (BATCH*SEQ)    // 4096
#define KVHEAD  192            // DH + NOPE per head in KV

// ---------------- scratch (static __device__ arrays: allowed) ----------------
__device__ float g_cq[(size_t)MROWS*QPROJ];
__device__ float g_Q[(size_t)MROWS*DMODEL];
__device__ float g_kvlora[(size_t)MROWS*KVPROJ];
__device__ float g_KV[(size_t)MROWS*KVOUT];
__device__ float g_Krope[(size_t)MROWS*ROPE_D];
__device__ float g_attnout[(size_t)MROWS*DMODEL];
// transposed weights (computed per launch; weights are inputs so this is deterministic)
__device__ float g_WdqT [(size_t)QPROJ*DMODEL];     // [1024][2048]
__device__ float g_WuqT [(size_t)DMODEL*QPROJ];     // [2048][1024]
__device__ float g_WdkvT[(size_t)CKV_COLS*DMODEL];  // [1429][2048]
__device__ float g_WukvT[(size_t)KVOUT*KVPROJ];     // [3072][1365]

#define BUF_CQ    0
#define BUF_Q     1
#define BUF_KVL   2
#define BUF_KV    3
#define BUF_KROPE 4
#define BUF_AOUT  5
#define BUF_WDQT  6
#define BUF_WUQT  7
#define BUF_WDKVT 8
#define BUF_WUKVT 9

__device__ __forceinline__ float* sel_buf(int s) {
    switch (s) {
        case BUF_CQ:    return g_cq;
        case BUF_Q:     return g_Q;
        case BUF_KVL:   return g_kvlora;
        case BUF_KV:    return g_KV;
        case BUF_KROPE: return g_Krope;
        case BUF_AOUT:  return g_attnout;
        case BUF_WDQT:  return g_WdqT;
        case BUF_WUQT:  return g_WuqT;
        case BUF_WDKVT: return g_WdkvT;
        default:        return g_WukvT;
    }
}

// =====================================================================
// Weight transpose: out[n][k] = in[k][n].  in is [K][N]. 32x32 tiles.
// =====================================================================
__global__ __launch_bounds__(256)
void transpose_kernel(const float* __restrict__ in, int outSel, int K, int N)
{
    __shared__ float t[32][33];
    float* out = sel_buf(outSel);
    int x  = blockIdx.x * 32 + threadIdx.x;   // n
    int y0 = blockIdx.y * 32;                 // k base
#pragma unroll
    for (int j = threadIdx.y; j < 32; j += 8)
        t[j][threadIdx.x] = (x < N && y0 + j < K) ? in[(size_t)(y0 + j) * N + x] : 0.f;
    __syncthreads();
    int x2 = blockIdx.y * 32 + threadIdx.x;   // k
    int y2 = blockIdx.x * 32;                 // n base
#pragma unroll
    for (int j = threadIdx.y; j < 32; j += 8)
        if (x2 < K && y2 + j < N) out[(size_t)(y2 + j) * K + x2] = t[threadIdx.x][j];
}

// =====================================================================
// bf16x3 tensor-core GEMM (NT): C[M,N] = A[M,K] @ Bt[N,K]^T, fp32 accum.
// 128x128x32 block tile, 8 warps (2x4), warp tile 64x32, mma.m16n8k16.bf16.
// Split: v = hi + lo (both bf16); acc += aHi*bHi + aHi*bLo + aLo*bHi.
// VEC=true requires K%32==0 (float4 gmem loads); VEC=false handles any K/N.
// Assumes M % 128 == 0 (always 4096 here).
// =====================================================================
#define PADK 40   // smem row stride in bf16 elements (32 data + 8 pad)

__device__ __forceinline__ void mma_bf16(float* c, const uint32_t* a, const uint32_t* b)
{
    asm volatile(
        "mma.sync.aligned.m16n8k16.row.col.f32.bf16.bf16.f32 "
        "{%0,%1,%2,%3}, {%4,%5,%6,%7}, {%8,%9}, {%0,%1,%2,%3};\n"
        : "+f"(c[0]), "+f"(c[1]), "+f"(c[2]), "+f"(c[3])
        : "r"(a[0]), "r"(a[1]), "r"(a[2]), "r"(a[3]), "r"(b[0]), "r"(b[1]));
}

__device__ __forceinline__ void split_bf16(float v, __nv_bfloat16& h, __nv_bfloat16& l)
{
    h = __float2bfloat16(v);
    l = __float2bfloat16(v - __bfloat162float(h));
}

template<bool VEC>
__global__ __launch_bounds__(256)
void gemm_bf16x3(const float* __restrict__ Aext, const float* __restrict__ Bext,
                 float* __restrict__ Cext, int aSel, int bSel, int cSel,
                 int M, int N, int K)
{
    const float* __restrict__ A  = (aSel >= 0) ? sel_buf(aSel) : Aext;
    const float* __restrict__ Bt = (bSel >= 0) ? sel_buf(bSel) : Bext;
    float* __restrict__       C  = (cSel >= 0) ? sel_buf(cSel) : Cext;

    __shared__ __align__(16) __nv_bfloat16 AsHi[128 * PADK];
    __shared__ __align__(16) __nv_bfloat16 AsLo[128 * PADK];
    __shared__ __align__(16) __nv_bfloat16 BsHi[128 * PADK];
    __shared__ __align__(16) __nv_bfloat16 BsLo[128 * PADK];

    const int tid  = threadIdx.x;
    const int lane = tid & 31;
    const int warp = tid >> 5;
    const int g    = lane >> 2;     // group (row within 8)
    const int tig  = lane & 3;      // thread in group
    const int wm   = (warp & 1) * 64;
    const int wn   = (warp >> 1) * 32;
    const int m0   = blockIdx.y * 128;
    const int n0   = blockIdx.x * 128;

    float acc[4][4][4];
#pragma unroll
    for (int mt = 0; mt < 4; mt++)
#pragma unroll
        for (int nt = 0; nt < 4; nt++)
#pragma unroll
            for (int i = 0; i < 4; i++) acc[mt][nt][i] = 0.f;

    const int nk = (K + 31) >> 5;

    float4 aV[4], bV[4];     // VEC prefetch regs
    float  aS[16], bS[16];   // scalar prefetch regs

    auto loadTile = [&](int kt) {
        const int k0 = kt << 5;
        if (VEC) {
#pragma unroll
            for (int p = 0; p < 4; p++) {
                int lin = tid + p * 256;
                int r = lin >> 3, c4 = (lin & 7) << 2;
                aV[p] = *(const float4*)&A[(size_t)(m0 + r) * K + k0 + c4];
                bV[p] = (n0 + r < N)
                      ? *(const float4*)&Bt[(size_t)(n0 + r) * K + k0 + c4]
                      : make_float4(0.f, 0.f, 0.f, 0.f);
            }
        } else {
#pragma unroll
            for (int p = 0; p < 16; p++) {
                int lin = tid + p * 256;
                int r = lin >> 5, c = lin & 31;
                aS[p] = (k0 + c < K) ? A[(size_t)(m0 + r) * K + k0 + c] : 0.f;
                bS[p] = (n0 + r < N && k0 + c < K)
                      ? Bt[(size_t)(n0 + r) * K + k0 + c] : 0.f;
            }
        }
    };

    auto storeTile = [&]() {
        if (VEC) {
#pragma unroll
            for (int p = 0; p < 4; p++) {
                int lin = tid + p * 256;
                int r = lin >> 3, c4 = (lin & 7) << 2;
                float va[4] = {aV[p].x, aV[p].y, aV[p].z, aV[p].w};
                float vb[4] = {bV[p].x, bV[p].y, bV[p].z, bV[p].w};
#pragma unroll
                for (int i = 0; i < 4; i++) {
                    split_bf16(va[i], AsHi[r * PADK + c4 + i], AsLo[r * PADK + c4 + i]);
                    split_bf16(vb[i], BsHi[r * PADK + c4 + i], BsLo[r * PADK + c4 + i]);
                }
            }
        } else {
#pragma unroll
            for (int p = 0; p < 16; p++) {
                int lin = tid + p * 256;
                int r = lin >> 5, c = lin & 31;
                split_bf16(aS[p], AsHi[r * PADK + c], AsLo[r * PADK + c]);
                split_bf16(bS[p], BsHi[r * PADK + c], BsLo[r * PADK + c]);
            }
        }
    };

    loadTile(0);
    for (int kt = 0; kt < nk; kt++) {
        storeTile();
        __syncthreads();
        if (kt + 1 < nk) loadTile(kt + 1);   // overlap next-tile LDGs with MMA

#pragma unroll
        for (int kk = 0; kk < 32; kk += 16) {
            uint32_t aHi[4][4], aLo[4][4], bHi[4][2], bLo[4][2];
#pragma unroll
            for (int mt = 0; mt < 4; mt++) {
                int rA = (wm + mt * 16 + g) * PADK + kk + 2 * tig;
                aHi[mt][0] = *(const uint32_t*)&AsHi[rA];
                aHi[mt][1] = *(const uint32_t*)&AsHi[rA + 8 * PADK];
                aHi[mt][2] = *(const uint32_t*)&AsHi[rA + 8];
                aHi[mt][3] = *(const uint32_t*)&AsHi[rA + 8 * PADK + 8];
                aLo[mt][0] = *(const uint32_t*)&AsLo[rA];
                aLo[mt][1] = *(const uint32_t*)&AsLo[rA + 8 * PADK];
                aLo[mt][2] = *(const uint32_t*)&AsLo[rA + 8];
                aLo[mt][3] = *(const uint32_t*)&AsLo[rA + 8 * PADK + 8];
            }
#pragma unroll
            for (int nt = 0; nt < 4; nt++) {
                int rB = (wn + nt * 8 + g) * PADK + kk + 2 * tig;
                bHi[nt][0] = *(const uint32_t*)&BsHi[rB];
                bHi[nt][1] = *(const uint32_t*)&BsHi[rB + 8];
                bLo[nt][0] = *(const uint32_t*)&BsLo[rB];
                bLo[nt][1] = *(const uint32_t*)&BsLo[rB + 8];
            }
#pragma unroll
            for (int mt = 0; mt < 4; mt++)
#pragma unroll
                for (int nt = 0; nt < 4; nt++) {
                    mma_bf16(acc[mt][nt], aHi[mt], bHi[nt]);
                    mma_bf16(acc[mt][nt], aHi[mt], bLo[nt]);
                    mma_bf16(acc[mt][nt], aLo[mt], bHi[nt]);
                }
        }
        __syncthreads();
    }

    // epilogue. c0,c1: (row g, cols 2tig,2tig+1); c2,c3: row g+8.
    if ((N & 1) == 0) {     // even N here is always a multiple of 128 -> full tiles
#pragma unroll
        for (int mt = 0; mt < 4; mt++)
#pragma unroll
            for (int nt = 0; nt < 4; nt++) {
                int r = m0 + wm + mt * 16 + g;
                int c = n0 + wn + nt * 8 + 2 * tig;
                *(float2*)&C[(size_t)r * N + c] =
                    make_float2(acc[mt][nt][0], acc[mt][nt][1]);
                *(float2*)&C[(size_t)(r + 8) * N + c] =
                    make_float2(acc[mt][nt][2], acc[mt][nt][3]);
            }
    } else {                // odd N (1429): scalar guarded stores
#pragma unroll
        for (int mt = 0; mt < 4; mt++)
#pragma unroll
            for (int nt = 0; nt < 4; nt++) {
                int r = m0 + wm + mt * 16 + g;
                int c = n0 + wn + nt * 8 + 2 * tig;
                if (c < N)     C[(size_t)r * N + c]           = acc[mt][nt][0];
                if (c + 1 < N) C[(size_t)r * N + c + 1]       = acc[mt][nt][1];
                if (c < N)     C[(size_t)(r + 8) * N + c]     = acc[mt][nt][2];
                if (c + 1 < N) C[(size_t)(r + 8) * N + c + 1] = acc[mt][nt][3];
            }
    }
}

// =====================================================================
// Row LayerNorm: y = (x - mean)/sqrt(var + eps) * w + b.  One block per row.
// =====================================================================
__global__ __launch_bounds__(256)
void ln_kernel(const float* __restrict__ inExt, float* __restrict__ outExt,
               int inSel, int outSel,
               const float* __restrict__ w, const float* __restrict__ b,
               int cols, int in_stride, int out_stride)
{
    const float* in  = (inSel  >= 0) ? sel_buf(inSel)  : inExt;
    float*       out = (outSel >= 0) ? sel_buf(outSel) : outExt;

    __shared__ float rs[32], rs2[32];
    const size_t row = blockIdx.x;
    const float* x = in  + row * (size_t)in_stride;
    float*       y = out + row * (size_t)out_stride;

    float s = 0.f, s2 = 0.f;
    for (int c = threadIdx.x; c < cols; c += blockDim.x) {
        float v = x[c]; s += v; s2 += v * v;
    }
#pragma unroll
    for (int o = 16; o; o >>= 1) {
        s  += __shfl_xor_sync(0xffffffffu, s,  o);
        s2 += __shfl_xor_sync(0xffffffffu, s2, o);
    }
    int lane = threadIdx.x & 31, wid = threadIdx.x >> 5;
    if (lane == 0) { rs[wid] = s; rs2[wid] = s2; }
    __syncthreads();
    if (wid == 0) {
        int nw = blockDim.x >> 5;
        s  = (lane < nw) ? rs[lane]  : 0.f;
        s2 = (lane < nw) ? rs2[lane] : 0.f;
#pragma unroll
        for (int o = 16; o; o >>= 1) {
            s  += __shfl_xor_sync(0xffffffffu, s,  o);
            s2 += __shfl_xor_sync(0xffffffffu, s2, o);
        }
        if (lane == 0) { rs[0] = s; rs2[0] = s2; }
    }
    __syncthreads();
    float mean = rs[0] / (float)cols;
    float var  = rs2[0] / (float)cols - mean * mean;
    float inv  = rsqrtf(var + 1e-5f);
    for (int c = threadIdx.x; c < cols; c += blockDim.x)
        y[c] = (x[c] - mean) * inv * w[c] + b[c];
}

// =====================================================================
// RoPE on Q (g_Q, in place). 512 thr = 16 heads x 32 lanes; block per (b,s).
// =====================================================================
__global__ __launch_bounds__(512)
void rope_q_kernel()
{
    int bs = blockIdx.x;
    int s  = bs & (SEQ - 1);
    int h  = threadIdx.x >> 5;
    int j  = threadIdx.x & 31;
    double f   = pow(10000.0, -(double)j / 64.0);
    double ang = (double)s * f;
    double cd, sd; sincos(ang, &sd, &cd);
    float c = (float)cd, sn = (float)sd;
    float* q = g_Q + (size_t)bs * DMODEL + h * DH + NOPE;
    float x1 = q[j], x2 = q[j + 32];
    q[j]      = x1 * c - x2 * sn;
    q[j + 32] = x2 * c + x1 * sn;
}

// RoPE on K_rope: compressed_kv[:, 1365:1429] -> g_Krope[b*S+s, 64]
__global__ __launch_bounds__(32)
void rope_k_kernel(const float* __restrict__ ckv)
{
    int bs = blockIdx.x;
    int s  = bs & (SEQ - 1);
    int j  = threadIdx.x;
    double f   = pow(10000.0, -(double)j / 64.0);
    double ang = (double)s * f;
    double cd, sd; sincos(ang, &sd, &cd);
    float c = (float)cd, sn = (float)sd;
    const float* src = ckv + (size_t)bs * CKV_COLS + KVPROJ;
    float x1 = src[j], x2 = src[j + 32];
    float* dst = g_Krope + (size_t)bs * ROPE_D;
    dst[j]      = x1 * c - x2 * sn;
    dst[j + 32] = x2 * c + x1 * sn;
}

// =====================================================================
// Flash attention (causal). BM=BN=64, dh=128. Unchanged from R7 baseline.
// =====================================================================
#define FL_KSTR 136
#define FLASH_SMEM ((64*128 + 64*FL_KSTR + 64*FL_KSTR + 64*64) * 4)

__global__ __launch_bounds__(256)
void flash_kernel()
{
    extern __shared__ float sm[];
    float* Qs = sm;                   // [64][128]
    float* Ks = Qs + 64*128;          // [64][136]
    float* Vs = Ks + 64*FL_KSTR;      // [64][136]
    float* Ps = Vs + 64*FL_KSTR;      // [64][64]

    const float* __restrict__ Q     = g_Q;
    const float* __restrict__ KV    = g_KV;
    const float* __restrict__ Krope = g_Krope;
    float*       __restrict__ Out   = g_attnout;

    const int q0 = blockIdx.x * 64;
    const int h  = blockIdx.y;
    const int b  = blockIdx.z;
    const int tid = threadIdx.x;
    const int tx = tid & 15;
    const int ty = tid >> 4;
    const float scale = 0.08838834764831845f;  // 1/sqrt(128)

    for (int i = tid; i < 64 * 128; i += 256) {
        int r = i >> 7, c = i & 127;
        Qs[i] = Q[((size_t)(b * SEQ + q0 + r)) * DMODEL + h * DH + c];
    }

    float m[4], l[4], O[4][8];
#pragma unroll
    for (int i = 0; i < 4; i++) {
        m[i] = -1e30f; l[i] = 0.f;
#pragma unroll
        for (int j = 0; j < 8; j++) O[i][j] = 0.f;
    }
    __syncthreads();

    const int ktiles = blockIdx.x + 1;
    for (int kt = 0; kt < ktiles; ++kt) {
        const int k0 = kt * 64;
        for (int i = tid; i < 64 * 128; i += 256) {
            int r = i >> 7, c = i & 127;
            size_t row = (size_t)(b * SEQ + k0 + r);
            float kv = (c < 64) ? KV[row * KVOUT + h * KVHEAD + c]
                                : Krope[row * ROPE_D + (c - 64)];
            Ks[r * FL_KSTR + c] = kv;
            Vs[r * FL_KSTR + c] = KV[row * KVOUT + h * KVHEAD + NOPE + c];
        }
        __syncthreads();

        float sc[4][4];
#pragma unroll
        for (int i = 0; i < 4; i++)
#pragma unroll
            for (int j = 0; j < 4; j++) sc[i][j] = 0.f;

        for (int k = 0; k < 128; k += 4) {
            float4 qa[4], kb[4];
#pragma unroll
            for (int i = 0; i < 4; i++) qa[i] = *(const float4*)&Qs[(ty*4 + i)*128 + k];
#pragma unroll
            for (int j = 0; j < 4; j++) kb[j] = *(const float4*)&Ks[(tx*4 + j)*FL_KSTR + k];
#pragma unroll
            for (int i = 0; i < 4; i++)
#pragma unroll
                for (int j = 0; j < 4; j++) {
                    sc[i][j] = fmaf(qa[i].x, kb[j].x, sc[i][j]);
                    sc[i][j] = fmaf(qa[i].y, kb[j].y, sc[i][j]);
                    sc[i][j] = fmaf(qa[i].z, kb[j].z, sc[i][j]);
                    sc[i][j] = fmaf(qa[i].w, kb[j].w, sc[i][j]);
                }
        }

#pragma unroll
        for (int i = 0; i < 4; i++) {
            int qi = q0 + ty*4 + i;
            float rowmax = -1e30f;
#pragma unroll
            for (int j = 0; j < 4; j++) {
                int kj = k0 + tx*4 + j;
                sc[i][j] = (kj <= qi) ? sc[i][j] * scale : -1e30f;
                rowmax = fmaxf(rowmax, sc[i][j]);
            }
#pragma unroll
            for (int o = 1; o < 16; o <<= 1)
                rowmax = fmaxf(rowmax, __shfl_xor_sync(0xffffffffu, rowmax, o, 16));
            float mnew = fmaxf(m[i], rowmax);
            float fac  = __expf(m[i] - mnew);
            float rsum = 0.f;
#pragma unroll
            for (int j = 0; j < 4; j++) {
                float p = __expf(sc[i][j] - mnew);
                Ps[(ty*4 + i)*64 + tx*4 + j] = p;
                rsum += p;
            }
#pragma unroll
            for (int o = 1; o < 16; o <<= 1)
                rsum += __shfl_xor_sync(0xffffffffu, rsum, o, 16);
            l[i] = l[i] * fac + rsum;
            m[i] = mnew;
#pragma unroll
            for (int j = 0; j < 8; j++) O[i][j] *= fac;
        }
        __syncthreads();

        for (int kc = 0; kc < 64; kc++) {
            float4 v0 = *(const float4*)&Vs[kc*FL_KSTR + tx*8];
            float4 v1 = *(const float4*)&Vs[kc*FL_KSTR + tx*8 + 4];
#pragma unroll
            for (int i = 0; i < 4; i++) {
                float p = Ps[(ty*4 + i)*64 + kc];
                O[i][0] = fmaf(p, v0.x, O[i][0]);
                O[i][1] = fmaf(p, v0.y, O[i][1]);
                O[i][2] = fmaf(p, v0.z, O[i][2]);
                O[i][3] = fmaf(p, v0.w, O[i][3]);
                O[i][4] = fmaf(p, v1.x, O[i][4]);
                O[i][5] = fmaf(p, v1.y, O[i][5]);
                O[i][6] = fmaf(p, v1.z, O[i][6]);
                O[i][7] = fmaf(p, v1.w, O[i][7]);
            }
        }
        __syncthreads();
    }

#pragma unroll
    for (int i = 0; i < 4; i++) {
        float inv = 1.f / l[i];
        size_t base = ((size_t)(b * SEQ + q0 + ty*4 + i)) * DMODEL + h * DH + tx*8;
#pragma unroll
        for (int j = 0; j < 8; j++) Out[base + j] = O[i][j] * inv;
    }
}

// =====================================================================
// Launch
// =====================================================================
extern "C" void kernel_launch(void* const* d_in, const int* in_sizes, int n_in,
                              void* d_out, int out_size)
{
    const float* x       = (const float*)d_in[0];
    const float* W_dq    = (const float*)d_in[1];
    const float* W_uq    = (const float*)d_in[2];
    const float* q_ln_w  = (const float*)d_in[3];
    const float* q_ln_b  = (const float*)d_in[4];
    const float* W_dkv   = (const float*)d_in[5];
    const float* W_ukv   = (const float*)d_in[6];
    const float* kv_ln_w = (const float*)d_in[7];
    const float* kv_ln_b = (const float*)d_in[8];
    const float* W_o     = (const float*)d_in[9];

    float* out = (float*)d_out;                      // [4096, 2048]
    float* ckv = out + (size_t)MROWS * DMODEL;       // [4096, 1429] compressed_kv

    cudaFuncSetAttribute(flash_kernel,
                         cudaFuncAttributeMaxDynamicSharedMemorySize, FLASH_SMEM);

    dim3 tb(256), tt(32, 8);

    // 0) transpose weights to [N][K] form for the NT tensor-core GEMM
    transpose_kernel<<<dim3((QPROJ+31)/32,   (DMODEL+31)/32), tt>>>(W_dq,  BUF_WDQT,  DMODEL, QPROJ);
    transpose_kernel<<<dim3((DMODEL+31)/32,  (QPROJ+31)/32),  tt>>>(W_uq,  BUF_WUQT,  QPROJ,  DMODEL);
    transpose_kernel<<<dim3((CKV_COLS+31)/32,(DMODEL+31)/32), tt>>>(W_dkv, BUF_WDKVT, DMODEL, CKV_COLS);
    transpose_kernel<<<dim3((KVOUT+31)/32,   (KVPROJ+31)/32), tt>>>(W_ukv, BUF_WUKVT, KVPROJ, KVOUT);

    // 1) cq_pre = x @ W_dq            [4096,1024] K=2048
    gemm_bf16x3<true><<<dim3(QPROJ/128, MROWS/128), tb>>>(
        x, nullptr, nullptr, -1, BUF_WDQT, BUF_CQ, MROWS, QPROJ, DMODEL);
    // 2) cq = LN(cq_pre) in place
    ln_kernel<<<MROWS, 256>>>(nullptr, nullptr, BUF_CQ, BUF_CQ,
                              q_ln_w, q_ln_b, QPROJ, QPROJ, QPROJ);
    // 3) Q = cq @ W_uq                [4096,2048] K=1024
    gemm_bf16x3<true><<<dim3(DMODEL/128, MROWS/128), tb>>>(
        nullptr, nullptr, nullptr, BUF_CQ, BUF_WUQT, BUF_Q, MROWS, DMODEL, QPROJ);
    // 4) RoPE(Q)
    rope_q_kernel<<<MROWS, 512>>>();
    // 5) compressed_kv = x @ W_dkv    [4096,1429] K=2048 (odd N -> scalar epilogue)
    gemm_bf16x3<true><<<dim3((CKV_COLS+127)/128, MROWS/128), tb>>>(
        x, nullptr, ckv, -1, BUF_WDKVT, -1, MROWS, CKV_COLS, DMODEL);
    // 6) kv_lora = LN(ckv[:, :1365])
    ln_kernel<<<MROWS, 256>>>(ckv, nullptr, -1, BUF_KVL,
                              kv_ln_w, kv_ln_b, KVPROJ, CKV_COLS, KVPROJ);
    // 7) K_rope = RoPE(ckv[:, 1365:])
    rope_k_kernel<<<MROWS, 32>>>(ckv);
    // 8) KV = kv_lora @ W_ukv         [4096,3072] K=1365 (K%32!=0 -> scalar loads)
    gemm_bf16x3<false><<<dim3(KVOUT/128, MROWS/128), tb>>>(
        nullptr, nullptr, nullptr, BUF_KVL, BUF_WUKVT, BUF_KV, MROWS, KVOUT, KVPROJ);
    // 9) causal flash attention -> g_attnout
    flash_kernel<<<dim3(SEQ/64, NHEADS, BATCH), tb, FLASH_SMEM>>>();
    // 10) out = attn_out @ W_o^T      (W_o is already [N][K] = [2048][2048])
    gemm_bf16x3<true><<<dim3(DMODEL/128, MROWS/128), tb>>>(
        nullptr, W_o, out, BUF_AOUT, -1, -1, MROWS, DMODEL, DMODEL);
}